// round 11
// baseline (speedup 1.0000x reference)
#include <cuda_runtime.h>
#include <cuda_fp16.h>

#define DD 64
#define NU 50000
#define NB 20000
#define NI 40000
// Unified row namespace: g0 (U+I) | g1 (U+B) | g2 (U+B) | agg (B)
#define R1 90000
#define R2 160000
#define R3 230000
#define NROWS 250000
#define NPROWS 230000
#define X16Q (NPROWS * 16)
#define EMAX 5200000
#define NBLK 62
#define NZ4 62500
#define T 256

// ---- device scratch (no allocation; zero-initialized at load) ----
__device__ __half g_x16  [(size_t)NPROWS * DD];  // x0 * nf (fp16)
__device__ __half g_f116 [(size_t)NPROWS * DD];  // layer-1 sources (fp16, col-scaled)
__device__ __half g_ili  [(size_t)NI * DD];      // IL_i for aggregation
__device__ __half g_acc16[(size_t)NPROWS * DD];  // fp16 accumulator
__device__ int    g_ecol[EMAX];
__device__ int    g_lo  [EMAX];
__device__ int    g_cnt [NROWS];
__device__ int    g_rowptr[NROWS + 1];
__device__ unsigned long long g_bstate[NBLK];
// degree-sort state
__device__ int    g_dbins[256];
__device__ int    g_dcur [256];
__device__ int    g_doff [256];
__device__ int    g_rowperm[NPROWS];

static inline unsigned gdiv(long long a, int b) { return (unsigned)((a + b - 1) / b); }

// ---------------- histogram (+ zero degree-sort state) ----------------
__global__ void k_hist(const int* __restrict__ r0, const int* __restrict__ r1p,
                       const int* __restrict__ r2p, const int* __restrict__ r3p,
                       int o1, int o2, int o3, int etot) {
    int t = blockIdx.x * blockDim.x + threadIdx.x;
    if (t >= etot) {
        int z = t - etot;
        if (z < 256) g_dbins[z] = 0;
        else if (z < 512) g_dcur[z - 256] = 0;
        return;
    }
    const int* rp; int e, ro;
    if (t < o1)      { rp = r0;  e = t;      ro = 0;  }
    else if (t < o2) { rp = r1p; e = t - o1; ro = R1; }
    else if (t < o3) { rp = r2p; e = t - o2; ro = R2; }
    else             { rp = r3p; e = t - o3; ro = R3; }
    int grow = __ldg(rp + e) + ro;
    int slot = atomicAdd(&g_cnt[grow], 1);
    g_lo[t] = (grow << 8) | slot;
}

// ---------------- single-pass decoupled-lookback exclusive scan ----------------
__global__ void __launch_bounds__(1024) k_scan() {
    __shared__ int wsum[32];
    __shared__ int s_prefix, s_agg;
    int tid = threadIdx.x, lane = tid & 31, wid = tid >> 5;
    int bid = blockIdx.x;
    int i0 = bid * 4096 + tid * 4;
    int v[4];
    #pragma unroll
    for (int j = 0; j < 4; j++) v[j] = (i0 + j < NROWS) ? g_cnt[i0 + j] : 0;
    int tsum = v[0] + v[1] + v[2] + v[3];
    int sc = tsum;
    #pragma unroll
    for (int o = 1; o < 32; o <<= 1) {
        int u = __shfl_up_sync(0xffffffffu, sc, o);
        if (lane >= o) sc += u;
    }
    if (lane == 31) wsum[wid] = sc;
    __syncthreads();
    if (wid == 0) {
        int ws = wsum[lane];
        int sw = ws;
        #pragma unroll
        for (int o = 1; o < 32; o <<= 1) {
            int u = __shfl_up_sync(0xffffffffu, sw, o);
            if (lane >= o) sw += u;
        }
        wsum[lane] = sw - ws;
        int agg = __shfl_sync(0xffffffffu, sw, 31);
        if (lane == 0) s_agg = agg;
        if (lane == 0)
            atomicExch(&g_bstate[bid],
                       (bid == 0 ? (2ULL << 32) : (1ULL << 32)) | (unsigned)agg);
        int prefix = 0;
        if (bid > 0) {
            int j = bid - 1;
            for (;;) {
                int idx = j - lane;
                unsigned long long s = (idx >= 0) ? atomicAdd(&g_bstate[idx], 0ULL)
                                                  : (2ULL << 32);
                unsigned flag = (unsigned)(s >> 32);
                unsigned invb = __ballot_sync(0xffffffffu, flag == 0u);
                unsigned preb = __ballot_sync(0xffffffffu, flag == 2u);
                int p  = preb ? (__ffs(preb) - 1) : 32;
                int iv = invb ? (__ffs(invb) - 1) : 32;
                if (iv < p) continue;
                int cnt = (p < 32) ? (p + 1) : 32;
                int val = (lane < cnt) ? (int)(s & 0xffffffffu) : 0;
                #pragma unroll
                for (int o = 16; o; o >>= 1) val += __shfl_xor_sync(0xffffffffu, val, o);
                prefix += val;
                if (p < 32) break;
                j -= 32;
            }
            if (lane == 0)
                atomicExch(&g_bstate[bid], (2ULL << 32) | (unsigned)(prefix + agg));
        }
        if (lane == 0) s_prefix = prefix;
    }
    __syncthreads();
    int excl = s_prefix + wsum[wid] + (sc - tsum);
    #pragma unroll
    for (int j = 0; j < 4; j++) {
        if (i0 + j < NROWS) g_rowptr[i0 + j] = excl;
        excl += v[j];
    }
    if (bid == NBLK - 1 && tid == 0) g_rowptr[NROWS] = s_prefix + s_agg;
}

// ---------------- fused mid: scatter + fp16 prep + state zero + degree hist ----------------
__global__ void k_mid(const int* __restrict__ r0, const int* __restrict__ r1p,
                      const int* __restrict__ r2p, const int* __restrict__ r3p,
                      const float4* __restrict__ u, const float4* __restrict__ b,
                      const float4* __restrict__ itm,
                      int n0, int n1, int n2, int n3,
                      int o1, int o2, int o3, int etot) {
    int t = blockIdx.x * blockDim.x + threadIdx.x;
    if (t < etot) {
        const int* cp; int e, ro;
        if (t < o1)      { cp = r0  + n0; e = t;      ro = 0;  }
        else if (t < o2) { cp = r1p + n1; e = t - o1; ro = R1; }
        else if (t < o3) { cp = r2p + n2; e = t - o2; ro = R2; }
        else             { cp = r3p + n3; e = t - o3; ro = 0;  }
        int packed = g_lo[t];
        int pos = __ldg(g_rowptr + (packed >> 8)) + (packed & 255);
        g_ecol[pos] = __ldg(cp + e) + ro;
    } else if (t < etot + X16Q) {
        int q = t - etot;
        int grow = q >> 4, sub = q & 15;
        int d = __ldg(g_rowptr + grow + 1) - __ldg(g_rowptr + grow);
        float nf = (d > 0) ? 1.f / (sqrtf((float)d) + 1e-8f) : 1.f;
        int ro = (grow < R1) ? 0 : ((grow < R2) ? R1 : R2);
        int lrow = grow - ro;
        const float4* xp;
        if (lrow < NU)       xp = u + (size_t)lrow * 16;
        else if (grow < R1)  xp = itm + (size_t)(lrow - NU) * 16;
        else                 xp = b + (size_t)(lrow - NU) * 16;
        float4 v = __ldg(xp + sub);
        __half2 h0 = __float22half2_rn(make_float2(v.x * nf, v.y * nf));
        __half2 h1 = __float22half2_rn(make_float2(v.z * nf, v.w * nf));
        ((uint2*)g_x16)[q] = make_uint2(*(unsigned*)&h0, *(unsigned*)&h1);
    } else {
        int z = t - etot - X16Q;
        if (z < NZ4) ((int4*)g_cnt)[z] = make_int4(0, 0, 0, 0);
        else if (z < NZ4 + NBLK) g_bstate[z - NZ4] = 0ULL;
        else {
            int r = z - NZ4 - NBLK;
            if (r < NPROWS) {
                int deg = __ldg(g_rowptr + r + 1) - __ldg(g_rowptr + r);
                atomicAdd(&g_dbins[min(deg, 255)], 1);
            }
        }
    }
}

// ---------------- degree-sort: 256-bin scan + block-aggregated scatter ----------------
__global__ void k_dscan() {
    __shared__ int sh[256];
    int tid = threadIdx.x;
    int v = g_dbins[tid];
    sh[tid] = v;
    __syncthreads();
    for (int o = 1; o < 256; o <<= 1) {
        int u = (tid >= o) ? sh[tid - o] : 0;
        __syncthreads();
        sh[tid] += u;
        __syncthreads();
    }
    g_doff[tid] = sh[tid] - v;
}

__global__ void __launch_bounds__(1024) k_dscat() {
    __shared__ int sh_cnt[256];
    __shared__ int sh_base[256];
    int tid = threadIdx.x;
    if (tid < 256) sh_cnt[tid] = 0;
    __syncthreads();
    int r = blockIdx.x * 1024 + tid;
    int b = 0, rloc = 0;
    bool valid = (r < NPROWS);
    if (valid) {
        int deg = __ldg(g_rowptr + r + 1) - __ldg(g_rowptr + r);
        b = min(deg, 255);
        rloc = atomicAdd(&sh_cnt[b], 1);
    }
    __syncthreads();
    if (tid < 256 && sh_cnt[tid] > 0)
        sh_base[tid] = atomicAdd(&g_dcur[tid], sh_cnt[tid]);
    __syncthreads();
    if (valid)
        g_rowperm[g_doff[b] + sh_base[b] + rloc] = r;
}

// ---------------- gathers: 8 lanes/row, unroll 4 (round-9 proven form) ----------------
__device__ __forceinline__ void hadd8(float4& a, float4& b, uint4 raw) {
    __half2* h = (__half2*)&raw;
    float2 f0 = __half22float2(h[0]), f1 = __half22float2(h[1]);
    float2 f2 = __half22float2(h[2]), f3 = __half22float2(h[3]);
    a.x += f0.x; a.y += f0.y; a.z += f1.x; a.w += f1.y;
    b.x += f2.x; b.y += f2.y; b.z += f3.x; b.w += f3.y;
}

__device__ __forceinline__ void cvt8(float4& a, float4& b, uint4 raw) {
    __half2* h = (__half2*)&raw;
    float2 f0 = __half22float2(h[0]), f1 = __half22float2(h[1]);
    float2 f2 = __half22float2(h[2]), f3 = __half22float2(h[3]);
    a = make_float4(f0.x, f0.y, f1.x, f1.y);
    b = make_float4(f2.x, f2.y, f3.x, f3.y);
}

__device__ __forceinline__ uint4 pack8(float4 a, float4 b) {
    __half2 h0 = __float22half2_rn(make_float2(a.x, a.y));
    __half2 h1 = __float22half2_rn(make_float2(a.z, a.w));
    __half2 h2 = __float22half2_rn(make_float2(b.x, b.y));
    __half2 h3 = __float22half2_rn(make_float2(b.z, b.w));
    return make_uint4(*(unsigned*)&h0, *(unsigned*)&h1, *(unsigned*)&h2, *(unsigned*)&h3);
}

__device__ __forceinline__ void gather8(const uint4* __restrict__ src, int beg, int end,
                                        int lane, float4& sa, float4& sb) {
    sa = make_float4(0.f, 0.f, 0.f, 0.f);
    sb = make_float4(0.f, 0.f, 0.f, 0.f);
    int i = beg;
    for (; i + 4 <= end; i += 4) {
        int c0 = __ldg(g_ecol + i),     c1 = __ldg(g_ecol + i + 1);
        int c2 = __ldg(g_ecol + i + 2), c3 = __ldg(g_ecol + i + 3);
        uint4 x0 = __ldg(src + (size_t)c0 * 8 + lane);
        uint4 x1 = __ldg(src + (size_t)c1 * 8 + lane);
        uint4 x2 = __ldg(src + (size_t)c2 * 8 + lane);
        uint4 x3 = __ldg(src + (size_t)c3 * 8 + lane);
        hadd8(sa, sb, x0); hadd8(sa, sb, x1); hadd8(sa, sb, x2); hadd8(sa, sb, x3);
    }
    for (; i < end; i++) {
        uint4 x0 = __ldg(src + (size_t)__ldg(g_ecol + i) * 8 + lane);
        hadd8(sa, sb, x0);
    }
}

__device__ __forceinline__ float norm_inv8(float4 a, float4 b) {
    float ss = a.x * a.x + a.y * a.y + a.z * a.z + a.w * a.w
             + b.x * b.x + b.y * b.y + b.z * b.z + b.w * b.w;
    #pragma unroll
    for (int o = 4; o; o >>= 1) ss += __shfl_xor_sync(0xffffffffu, ss, o, 8);
    return 1.f / fmaxf(sqrtf(ss), 1e-12f);
}

// Layer 1: raw = gather(x16); f116 = raw*16*nf^2; acc16 = x16*rsf + normalize(raw)
__global__ void k_l1() {
    int t = blockIdx.x * blockDim.x + threadIdx.x;
    int wrow = t >> 3, lane = t & 7;
    if (wrow >= NPROWS) return;
    int row = __ldg(g_rowperm + wrow);
    int beg = __ldg(g_rowptr + row), end = __ldg(g_rowptr + row + 1);
    float4 sa, sb;
    gather8((const uint4*)g_x16, beg, end, lane, sa, sb);
    int deg = end - beg;
    float nf = (deg > 0) ? 1.f / (sqrtf((float)deg) + 1e-8f) : 1.f;
    float rsf = (deg > 0) ? (sqrtf((float)deg) + 1e-8f) : 1.f;
    float fs = 16.f * nf * nf;
    float inv = norm_inv8(sa, sb);
    ((uint4*)g_f116)[(size_t)row * 8 + lane] =
        pack8(make_float4(sa.x * fs, sa.y * fs, sa.z * fs, sa.w * fs),
              make_float4(sb.x * fs, sb.y * fs, sb.z * fs, sb.w * fs));
    uint4 xo = __ldg((const uint4*)g_x16 + (size_t)row * 8 + lane);
    float4 a0, a1;
    cvt8(a0, a1, xo);
    a0.x = a0.x * rsf + sa.x * inv; a0.y = a0.y * rsf + sa.y * inv;
    a0.z = a0.z * rsf + sa.z * inv; a0.w = a0.w * rsf + sa.w * inv;
    a1.x = a1.x * rsf + sb.x * inv; a1.y = a1.y * rsf + sb.y * inv;
    a1.z = a1.z * rsf + sb.z * inv; a1.w = a1.w * rsf + sb.w * inv;
    ((uint4*)g_acc16)[(size_t)row * 8 + lane] = pack8(a0, a1);
}

// Layer 2: raw2 = gather(f116); result = acc16 + normalize(raw2)
__global__ void k_l2(float* __restrict__ out) {
    int t = blockIdx.x * blockDim.x + threadIdx.x;
    int wrow = t >> 3, lane = t & 7;
    if (wrow >= NPROWS) return;
    int row = __ldg(g_rowperm + wrow);
    int beg = __ldg(g_rowptr + row), end = __ldg(g_rowptr + row + 1);
    float4 sa, sb;
    gather8((const uint4*)g_f116, beg, end, lane, sa, sb);
    float inv = norm_inv8(sa, sb);
    uint4 araw = ((const uint4*)g_acc16)[(size_t)row * 8 + lane];
    float4 a0, a1;
    cvt8(a0, a1, araw);
    a0.x += sa.x * inv; a0.y += sa.y * inv; a0.z += sa.z * inv; a0.w += sa.w * inv;
    a1.x += sb.x * inv; a1.y += sb.y * inv; a1.z += sb.z * inv; a1.w += sb.w * inv;
    if (row >= NU && row < R1) {
        ((uint4*)g_ili)[(size_t)(row - NU) * 8 + lane] = pack8(a0, a1);
        return;
    }
    float4* d;
    if (row < NU)            d = (float4*)out + (size_t)row * 16;
    else if (row < R1 + NU)  d = (float4*)out + ((size_t)NU + (row - R1)) * 16;
    else if (row < R2)       d = (float4*)out + ((size_t)3 * NU + NB + (row - R1 - NU)) * 16;
    else if (row < R2 + NU)  d = (float4*)out + ((size_t)2 * NU + (row - R2)) * 16;
    else                     d = (float4*)out + ((size_t)3 * NU + 2 * NB + (row - R2 - NU)) * 16;
    d[lane * 2]     = a0;
    d[lane * 2 + 1] = a1;
}

// Bundle aggregation: out[3U+b] = (1/max(deg,1)) * sum IL_i
__global__ void k_agg(float* __restrict__ out) {
    int t = blockIdx.x * blockDim.x + threadIdx.x;
    int row = t >> 3, lane = t & 7;
    if (row >= NB) return;
    int grow = R3 + row;
    int beg = __ldg(g_rowptr + grow), end = __ldg(g_rowptr + grow + 1);
    float4 sa, sb;
    gather8((const uint4*)g_ili, beg, end, lane, sa, sb);
    float fac = 1.f / fmaxf((float)(end - beg), 1.f);
    sa.x *= fac; sa.y *= fac; sa.z *= fac; sa.w *= fac;
    sb.x *= fac; sb.y *= fac; sb.z *= fac; sb.w *= fac;
    float4* d = (float4*)out + ((size_t)3 * NU + row) * 16;
    d[lane * 2]     = sa;
    d[lane * 2 + 1] = sb;
}

extern "C" void kernel_launch(void* const* d_in, const int* in_sizes, int n_in,
                              void* d_out, int out_size) {
    const float* users   = (const float*)d_in[0];
    const float* bundles = (const float*)d_in[1];
    const float* items   = (const float*)d_in[2];
    const int*   ui_idx  = (const int*)d_in[3];
    const int*   ub_idx  = (const int*)d_in[5];
    const int*   ubx_idx = (const int*)d_in[7];
    const int*   agg_idx = (const int*)d_in[9];
    int n0 = in_sizes[4], n1 = in_sizes[6], n2 = in_sizes[8], n3 = in_sizes[10];
    int o1 = n0, o2 = o1 + n1, o3 = o2 + n2, etot = o3 + n3;
    float* out = (float*)d_out;

    k_hist<<<gdiv((long long)etot + 512, T), T>>>(ui_idx, ub_idx, ubx_idx, agg_idx,
                                                  o1, o2, o3, etot);
    k_scan<<<NBLK, 1024>>>();
    long long midN = (long long)etot + X16Q + NZ4 + NBLK + NPROWS;
    k_mid<<<gdiv(midN, T), T>>>(ui_idx, ub_idx, ubx_idx, agg_idx,
                                (const float4*)users, (const float4*)bundles,
                                (const float4*)items,
                                n0, n1, n2, n3, o1, o2, o3, etot);
    k_dscan<<<1, 256>>>();
    k_dscat<<<gdiv(NPROWS, 1024), 1024>>>();
    k_l1<<<gdiv((long long)NPROWS * 8, T), T>>>();
    k_l2<<<gdiv((long long)NPROWS * 8, T), T>>>(out);
    k_agg<<<gdiv((long long)NB * 8, T), T>>>(out);
}

// round 12
// speedup vs baseline: 1.0578x; 1.0578x over previous
#include <cuda_runtime.h>
#include <cuda_fp16.h>

#define DD 64
#define NU 50000
#define NB 20000
#define NI 40000
// Unified row namespace: g0 (U+I) | g1 (U+B) | g2 (U+B) | agg (B)
#define R1 90000
#define R2 160000
#define R3 230000
#define NROWS 250000
#define NPROWS 230000
#define X16Q (NPROWS * 16)
#define ELLS 128            /* max degree; Poisson(<=40) tail < 80 */
#define T 256

// ---- device scratch (no allocation; zero-initialized at load) ----
__device__ __half g_x16  [(size_t)NPROWS * DD];  // x0 * nf (fp16)
__device__ __half g_f116 [(size_t)NPROWS * DD];  // layer-1 sources (fp16, col-scaled)
__device__ __half g_ili  [(size_t)NI * DD];      // IL_i for aggregation
__device__ __half g_acc16[(size_t)NPROWS * DD];  // fp16 accumulator
__device__ int    g_ell [(size_t)ELLS * NROWS];  // ELL edge columns
__device__ int    g_cnt [NROWS];                 // per-row degree counter (re-zeroed each call)
__device__ int    g_deg [NROWS];                 // degree snapshot for gathers

static inline unsigned gdiv(long long a, int b) { return (unsigned)((a + b - 1) / b); }

// ---------------- fused histogram + ELL scatter (single build pass) ----------------
__global__ void k_hist(const int* __restrict__ r0, const int* __restrict__ r1p,
                       const int* __restrict__ r2p, const int* __restrict__ r3p,
                       int n0, int n1, int n2, int n3,
                       int o1, int o2, int o3, int etot) {
    int t = blockIdx.x * blockDim.x + threadIdx.x;
    if (t >= etot) return;
    const int* rp; const int* cp; int e, ro, co;
    if (t < o1)      { rp = r0;  cp = r0  + n0; e = t;      ro = 0;  co = 0;  }
    else if (t < o2) { rp = r1p; cp = r1p + n1; e = t - o1; ro = R1; co = R1; }
    else if (t < o3) { rp = r2p; cp = r2p + n2; e = t - o2; ro = R2; co = R2; }
    else             { rp = r3p; cp = r3p + n3; e = t - o3; ro = R3; co = 0;  }
    int grow = __ldg(rp + e) + ro;
    int slot = atomicAdd(&g_cnt[grow], 1);
    g_ell[(size_t)slot * NROWS + grow] = __ldg(cp + e) + co;
}

// ---------------- prep: fp16 col-scaled features + deg snapshot + cnt re-zero ----------------
__global__ void k_prep(const float4* __restrict__ u, const float4* __restrict__ b,
                       const float4* __restrict__ itm) {
    int t = blockIdx.x * blockDim.x + threadIdx.x;
    if (t < X16Q) {
        int grow = t >> 4, sub = t & 15;
        int deg = g_cnt[grow];   // all 16 lanes of the row read in one warp instruction
        float nf = (deg > 0) ? 1.f / (sqrtf((float)deg) + 1e-8f) : 1.f;
        int ro = (grow < R1) ? 0 : ((grow < R2) ? R1 : R2);
        int lrow = grow - ro;
        const float4* xp;
        if (lrow < NU)       xp = u + (size_t)lrow * 16;
        else if (grow < R1)  xp = itm + (size_t)(lrow - NU) * 16;
        else                 xp = b + (size_t)(lrow - NU) * 16;
        float4 v = __ldg(xp + sub);
        __half2 h0 = __float22half2_rn(make_float2(v.x * nf, v.y * nf));
        __half2 h1 = __float22half2_rn(make_float2(v.z * nf, v.w * nf));
        ((uint2*)g_x16)[t] = make_uint2(*(unsigned*)&h0, *(unsigned*)&h1);
        if (sub == 0) { g_deg[grow] = deg; g_cnt[grow] = 0; }
    } else {
        int r = NPROWS + (t - X16Q);   // agg rows: deg snapshot + zero only
        if (r < NROWS) { g_deg[r] = g_cnt[r]; g_cnt[r] = 0; }
    }
}

// ---------------- gathers: 8 lanes/row, ELL cols, unroll 4 (round-9 proven core) ----------------
__device__ __forceinline__ void hadd8(float4& a, float4& b, uint4 raw) {
    __half2* h = (__half2*)&raw;
    float2 f0 = __half22float2(h[0]), f1 = __half22float2(h[1]);
    float2 f2 = __half22float2(h[2]), f3 = __half22float2(h[3]);
    a.x += f0.x; a.y += f0.y; a.z += f1.x; a.w += f1.y;
    b.x += f2.x; b.y += f2.y; b.z += f3.x; b.w += f3.y;
}

__device__ __forceinline__ void cvt8(float4& a, float4& b, uint4 raw) {
    __half2* h = (__half2*)&raw;
    float2 f0 = __half22float2(h[0]), f1 = __half22float2(h[1]);
    float2 f2 = __half22float2(h[2]), f3 = __half22float2(h[3]);
    a = make_float4(f0.x, f0.y, f1.x, f1.y);
    b = make_float4(f2.x, f2.y, f3.x, f3.y);
}

__device__ __forceinline__ uint4 pack8(float4 a, float4 b) {
    __half2 h0 = __float22half2_rn(make_float2(a.x, a.y));
    __half2 h1 = __float22half2_rn(make_float2(a.z, a.w));
    __half2 h2 = __float22half2_rn(make_float2(b.x, b.y));
    __half2 h3 = __float22half2_rn(make_float2(b.z, b.w));
    return make_uint4(*(unsigned*)&h0, *(unsigned*)&h1, *(unsigned*)&h2, *(unsigned*)&h3);
}

// ellrow: global row index into g_ell; deg: its degree
__device__ __forceinline__ void gather8(const uint4* __restrict__ src, int ellrow, int deg,
                                        int lane, float4& sa, float4& sb) {
    sa = make_float4(0.f, 0.f, 0.f, 0.f);
    sb = make_float4(0.f, 0.f, 0.f, 0.f);
    const int* ep = g_ell + ellrow;
    int s = 0;
    for (; s + 4 <= deg; s += 4) {
        int c0 = __ldg(ep + (size_t)s * NROWS);
        int c1 = __ldg(ep + (size_t)(s + 1) * NROWS);
        int c2 = __ldg(ep + (size_t)(s + 2) * NROWS);
        int c3 = __ldg(ep + (size_t)(s + 3) * NROWS);
        uint4 x0 = __ldg(src + (size_t)c0 * 8 + lane);
        uint4 x1 = __ldg(src + (size_t)c1 * 8 + lane);
        uint4 x2 = __ldg(src + (size_t)c2 * 8 + lane);
        uint4 x3 = __ldg(src + (size_t)c3 * 8 + lane);
        hadd8(sa, sb, x0); hadd8(sa, sb, x1); hadd8(sa, sb, x2); hadd8(sa, sb, x3);
    }
    for (; s < deg; s++) {
        int c0 = __ldg(ep + (size_t)s * NROWS);
        uint4 x0 = __ldg(src + (size_t)c0 * 8 + lane);
        hadd8(sa, sb, x0);
    }
}

__device__ __forceinline__ float norm_inv8(float4 a, float4 b) {
    float ss = a.x * a.x + a.y * a.y + a.z * a.z + a.w * a.w
             + b.x * b.x + b.y * b.y + b.z * b.z + b.w * b.w;
    #pragma unroll
    for (int o = 4; o; o >>= 1) ss += __shfl_xor_sync(0xffffffffu, ss, o, 8);
    return 1.f / fmaxf(sqrtf(ss), 1e-12f);
}

// Layer 1: raw = gather(x16); f116 = raw*16*nf^2; acc16 = x16*rsf + normalize(raw)
__global__ void k_l1() {
    int t = blockIdx.x * blockDim.x + threadIdx.x;
    int row = t >> 3, lane = t & 7;
    if (row >= NPROWS) return;
    int deg = __ldg(g_deg + row);
    float4 sa, sb;
    gather8((const uint4*)g_x16, row, deg, lane, sa, sb);
    float nf = (deg > 0) ? 1.f / (sqrtf((float)deg) + 1e-8f) : 1.f;
    float rsf = (deg > 0) ? (sqrtf((float)deg) + 1e-8f) : 1.f;
    float fs = 16.f * nf * nf;
    float inv = norm_inv8(sa, sb);
    ((uint4*)g_f116)[(size_t)row * 8 + lane] =
        pack8(make_float4(sa.x * fs, sa.y * fs, sa.z * fs, sa.w * fs),
              make_float4(sb.x * fs, sb.y * fs, sb.z * fs, sb.w * fs));
    uint4 xo = __ldg((const uint4*)g_x16 + (size_t)row * 8 + lane);
    float4 a0, a1;
    cvt8(a0, a1, xo);
    a0.x = a0.x * rsf + sa.x * inv; a0.y = a0.y * rsf + sa.y * inv;
    a0.z = a0.z * rsf + sa.z * inv; a0.w = a0.w * rsf + sa.w * inv;
    a1.x = a1.x * rsf + sb.x * inv; a1.y = a1.y * rsf + sb.y * inv;
    a1.z = a1.z * rsf + sb.z * inv; a1.w = a1.w * rsf + sb.w * inv;
    ((uint4*)g_acc16)[(size_t)row * 8 + lane] = pack8(a0, a1);
}

// Layer 2: raw2 = gather(f116); result = acc16 + normalize(raw2)
__global__ void k_l2(float* __restrict__ out) {
    int t = blockIdx.x * blockDim.x + threadIdx.x;
    int row = t >> 3, lane = t & 7;
    if (row >= NPROWS) return;
    int deg = __ldg(g_deg + row);
    float4 sa, sb;
    gather8((const uint4*)g_f116, row, deg, lane, sa, sb);
    float inv = norm_inv8(sa, sb);
    uint4 araw = ((const uint4*)g_acc16)[(size_t)row * 8 + lane];
    float4 a0, a1;
    cvt8(a0, a1, araw);
    a0.x += sa.x * inv; a0.y += sa.y * inv; a0.z += sa.z * inv; a0.w += sa.w * inv;
    a1.x += sb.x * inv; a1.y += sb.y * inv; a1.z += sb.z * inv; a1.w += sb.w * inv;
    if (row >= NU && row < R1) {
        ((uint4*)g_ili)[(size_t)(row - NU) * 8 + lane] = pack8(a0, a1);
        return;
    }
    float4* d;
    if (row < NU)            d = (float4*)out + (size_t)row * 16;
    else if (row < R1 + NU)  d = (float4*)out + ((size_t)NU + (row - R1)) * 16;
    else if (row < R2)       d = (float4*)out + ((size_t)3 * NU + NB + (row - R1 - NU)) * 16;
    else if (row < R2 + NU)  d = (float4*)out + ((size_t)2 * NU + (row - R2)) * 16;
    else                     d = (float4*)out + ((size_t)3 * NU + 2 * NB + (row - R2 - NU)) * 16;
    d[lane * 2]     = a0;
    d[lane * 2 + 1] = a1;
}

// Bundle aggregation: out[3U+b] = (1/max(deg,1)) * sum IL_i
__global__ void k_agg(float* __restrict__ out) {
    int t = blockIdx.x * blockDim.x + threadIdx.x;
    int row = t >> 3, lane = t & 7;
    if (row >= NB) return;
    int grow = R3 + row;
    int deg = __ldg(g_deg + grow);
    float4 sa, sb;
    gather8((const uint4*)g_ili, grow, deg, lane, sa, sb);
    float fac = 1.f / fmaxf((float)deg, 1.f);
    sa.x *= fac; sa.y *= fac; sa.z *= fac; sa.w *= fac;
    sb.x *= fac; sb.y *= fac; sb.z *= fac; sb.w *= fac;
    float4* d = (float4*)out + ((size_t)3 * NU + row) * 16;
    d[lane * 2]     = sa;
    d[lane * 2 + 1] = sb;
}

extern "C" void kernel_launch(void* const* d_in, const int* in_sizes, int n_in,
                              void* d_out, int out_size) {
    const float* users   = (const float*)d_in[0];
    const float* bundles = (const float*)d_in[1];
    const float* items   = (const float*)d_in[2];
    const int*   ui_idx  = (const int*)d_in[3];
    const int*   ub_idx  = (const int*)d_in[5];
    const int*   ubx_idx = (const int*)d_in[7];
    const int*   agg_idx = (const int*)d_in[9];
    int n0 = in_sizes[4], n1 = in_sizes[6], n2 = in_sizes[8], n3 = in_sizes[10];
    int o1 = n0, o2 = o1 + n1, o3 = o2 + n2, etot = o3 + n3;
    float* out = (float*)d_out;

    k_hist<<<gdiv(etot, T), T>>>(ui_idx, ub_idx, ubx_idx, agg_idx,
                                 n0, n1, n2, n3, o1, o2, o3, etot);
    k_prep<<<gdiv((long long)X16Q + (NROWS - NPROWS), T), T>>>(
        (const float4*)users, (const float4*)bundles, (const float4*)items);
    k_l1<<<gdiv((long long)NPROWS * 8, T), T>>>();
    k_l2<<<gdiv((long long)NPROWS * 8, T), T>>>(out);
    k_agg<<<gdiv((long long)NB * 8, T), T>>>(out);
}

// round 13
// speedup vs baseline: 1.1950x; 1.1296x over previous
#include <cuda_runtime.h>
#include <cuda_fp16.h>

#define DD 64
#define NU 50000
#define NB 20000
#define NI 40000
#define R1 90000
#define R2 160000
#define R3 230000
#define NROWS 250000
#define NPROWS 230000
// per-graph edge-region bases (capacities exceed exact sizes 2.0M/1.2M/1.6M/0.3M)
#define EB1 2050000
#define EB2 3300000
#define EB3 4950000
#define EMAX 5300000
#define T 256

// ---- device scratch (no allocation; zero-initialized at load) ----
__device__ __half g_x16  [(size_t)NPROWS * DD];
__device__ __half g_f116 [(size_t)NPROWS * DD];
__device__ __half g_ili  [(size_t)NI * DD];
__device__ __half g_acc16[(size_t)NPROWS * DD];
__device__ int    g_ecol[EMAX];
__device__ int    g_lo  [EMAX];
__device__ int    g_cnt [NROWS];       // degree counters; zeroed by last consumer
__device__ int    g_rowptr[NROWS];     // row start (includes edge-region base)
__device__ unsigned long long g_bstate[64];

static inline unsigned gdiv(long long a, int b) { return (unsigned)((a + b - 1) / b); }

// ---------------- per-graph histogram ----------------
__global__ void k_histg(const int* __restrict__ rows, int nE, int rowbase, int lobase) {
    int e = blockIdx.x * blockDim.x + threadIdx.x;
    if (e >= nE) return;
    int grow = __ldg(rows + e) + rowbase;
    int slot = atomicAdd(&g_cnt[grow], 1);
    g_lo[lobase + e] = (grow << 8) | slot;
}

// ---------------- per-graph decoupled-lookback exclusive scan ----------------
__global__ void __launch_bounds__(1024) k_scang(int rowbase, int nrows, int ebase, int bso) {
    __shared__ int wsum[32];
    __shared__ int s_prefix;
    int tid = threadIdx.x, lane = tid & 31, wid = tid >> 5;
    int bid = blockIdx.x;
    int i0 = bid * 4096 + tid * 4;
    int v[4];
    #pragma unroll
    for (int j = 0; j < 4; j++) v[j] = (i0 + j < nrows) ? g_cnt[rowbase + i0 + j] : 0;
    int tsum = v[0] + v[1] + v[2] + v[3];
    int sc = tsum;
    #pragma unroll
    for (int o = 1; o < 32; o <<= 1) {
        int u = __shfl_up_sync(0xffffffffu, sc, o);
        if (lane >= o) sc += u;
    }
    if (lane == 31) wsum[wid] = sc;
    __syncthreads();
    if (wid == 0) {
        int ws = wsum[lane];
        int sw = ws;
        #pragma unroll
        for (int o = 1; o < 32; o <<= 1) {
            int u = __shfl_up_sync(0xffffffffu, sw, o);
            if (lane >= o) sw += u;
        }
        wsum[lane] = sw - ws;
        int agg = __shfl_sync(0xffffffffu, sw, 31);
        if (lane == 0)
            atomicExch(&g_bstate[bso + bid],
                       (bid == 0 ? (2ULL << 32) : (1ULL << 32)) | (unsigned)agg);
        int prefix = 0;
        if (bid > 0) {
            int j = bid - 1;
            for (;;) {
                int idx = j - lane;
                unsigned long long s = (idx >= 0) ? atomicAdd(&g_bstate[bso + idx], 0ULL)
                                                  : (2ULL << 32);
                unsigned flag = (unsigned)(s >> 32);
                unsigned invb = __ballot_sync(0xffffffffu, flag == 0u);
                unsigned preb = __ballot_sync(0xffffffffu, flag == 2u);
                int p  = preb ? (__ffs(preb) - 1) : 32;
                int iv = invb ? (__ffs(invb) - 1) : 32;
                if (iv < p) continue;
                int cnt = (p < 32) ? (p + 1) : 32;
                int val = (lane < cnt) ? (int)(s & 0xffffffffu) : 0;
                #pragma unroll
                for (int o = 16; o; o >>= 1) val += __shfl_xor_sync(0xffffffffu, val, o);
                prefix += val;
                if (p < 32) break;
                j -= 32;
            }
            if (lane == 0)
                atomicExch(&g_bstate[bso + bid],
                           (2ULL << 32) | (unsigned)(prefix + agg));
        }
        if (lane == 0) s_prefix = prefix;
    }
    __syncthreads();
    int excl = s_prefix + wsum[wid] + (sc - tsum);
    #pragma unroll
    for (int j = 0; j < 4; j++) {
        if (i0 + j < nrows) g_rowptr[rowbase + i0 + j] = ebase + excl;
        excl += v[j];
    }
}

// ---------------- per-graph atomic-free scatter ----------------
__global__ void k_scatg(const int* __restrict__ cols, int nE, int lobase, int co) {
    int e = blockIdx.x * blockDim.x + threadIdx.x;
    if (e >= nE) return;
    int packed = g_lo[lobase + e];
    int pos = __ldg(g_rowptr + (packed >> 8)) + (packed & 255);
    g_ecol[pos] = __ldg(cols + e) + co;
}

// ---------------- per-graph prep: col-scaled fp16 features + bstate re-zero ----------------
__global__ void k_prepg(const float4* __restrict__ srcA, const float4* __restrict__ srcB,
                        int rowbase, int nrows, int zbase, int zcnt) {
    int t = blockIdx.x * blockDim.x + threadIdx.x;
    int nq = nrows * 16;
    if (t < nq) {
        int lrow = t >> 4, sub = t & 15;
        int grow = rowbase + lrow;
        int deg = g_cnt[grow];
        float nf = (deg > 0) ? 1.f / (sqrtf((float)deg) + 1e-8f) : 1.f;
        const float4* xp = (lrow < NU) ? srcA + (size_t)lrow * 16
                                       : srcB + (size_t)(lrow - NU) * 16;
        float4 v = __ldg(xp + sub);
        __half2 h0 = __float22half2_rn(make_float2(v.x * nf, v.y * nf));
        __half2 h1 = __float22half2_rn(make_float2(v.z * nf, v.w * nf));
        ((uint2*)g_x16)[(size_t)grow * 16 + sub] = make_uint2(*(unsigned*)&h0, *(unsigned*)&h1);
    } else {
        int z = t - nq;
        if (z < zcnt) g_bstate[zbase + z] = 0ULL;
    }
}

// ---------------- gathers: 8 lanes/row, unroll 4 (round-9 proven core) ----------------
__device__ __forceinline__ void hadd8(float4& a, float4& b, uint4 raw) {
    __half2* h = (__half2*)&raw;
    float2 f0 = __half22float2(h[0]), f1 = __half22float2(h[1]);
    float2 f2 = __half22float2(h[2]), f3 = __half22float2(h[3]);
    a.x += f0.x; a.y += f0.y; a.z += f1.x; a.w += f1.y;
    b.x += f2.x; b.y += f2.y; b.z += f3.x; b.w += f3.y;
}

__device__ __forceinline__ void cvt8(float4& a, float4& b, uint4 raw) {
    __half2* h = (__half2*)&raw;
    float2 f0 = __half22float2(h[0]), f1 = __half22float2(h[1]);
    float2 f2 = __half22float2(h[2]), f3 = __half22float2(h[3]);
    a = make_float4(f0.x, f0.y, f1.x, f1.y);
    b = make_float4(f2.x, f2.y, f3.x, f3.y);
}

__device__ __forceinline__ uint4 pack8(float4 a, float4 b) {
    __half2 h0 = __float22half2_rn(make_float2(a.x, a.y));
    __half2 h1 = __float22half2_rn(make_float2(a.z, a.w));
    __half2 h2 = __float22half2_rn(make_float2(b.x, b.y));
    __half2 h3 = __float22half2_rn(make_float2(b.z, b.w));
    return make_uint4(*(unsigned*)&h0, *(unsigned*)&h1, *(unsigned*)&h2, *(unsigned*)&h3);
}

__device__ __forceinline__ void gather8(const uint4* __restrict__ src, int beg, int end,
                                        int lane, float4& sa, float4& sb) {
    sa = make_float4(0.f, 0.f, 0.f, 0.f);
    sb = make_float4(0.f, 0.f, 0.f, 0.f);
    int i = beg;
    for (; i + 4 <= end; i += 4) {
        int c0 = __ldg(g_ecol + i),     c1 = __ldg(g_ecol + i + 1);
        int c2 = __ldg(g_ecol + i + 2), c3 = __ldg(g_ecol + i + 3);
        uint4 x0 = __ldg(src + (size_t)c0 * 8 + lane);
        uint4 x1 = __ldg(src + (size_t)c1 * 8 + lane);
        uint4 x2 = __ldg(src + (size_t)c2 * 8 + lane);
        uint4 x3 = __ldg(src + (size_t)c3 * 8 + lane);
        hadd8(sa, sb, x0); hadd8(sa, sb, x1); hadd8(sa, sb, x2); hadd8(sa, sb, x3);
    }
    for (; i < end; i++) {
        uint4 x0 = __ldg(src + (size_t)__ldg(g_ecol + i) * 8 + lane);
        hadd8(sa, sb, x0);
    }
}

__device__ __forceinline__ float norm_inv8(float4 a, float4 b) {
    float ss = a.x * a.x + a.y * a.y + a.z * a.z + a.w * a.w
             + b.x * b.x + b.y * b.y + b.z * b.z + b.w * b.w;
    #pragma unroll
    for (int o = 4; o; o >>= 1) ss += __shfl_xor_sync(0xffffffffu, ss, o, 8);
    return 1.f / fmaxf(sqrtf(ss), 1e-12f);
}

// Layer 1 (per graph): raw = gather(x16); f116 = raw*16*nf^2; acc16 = x16*rsf + normalize(raw)
__global__ void k_l1g(int rowbase, int nrows) {
    int t = blockIdx.x * blockDim.x + threadIdx.x;
    int lrow = t >> 3, lane = t & 7;
    if (lrow >= nrows) return;
    int row = rowbase + lrow;
    int beg = __ldg(g_rowptr + row);
    int deg = __ldg(g_cnt + row);
    float4 sa, sb;
    gather8((const uint4*)g_x16, beg, beg + deg, lane, sa, sb);
    float nf = (deg > 0) ? 1.f / (sqrtf((float)deg) + 1e-8f) : 1.f;
    float rsf = (deg > 0) ? (sqrtf((float)deg) + 1e-8f) : 1.f;
    float fs = 16.f * nf * nf;
    float inv = norm_inv8(sa, sb);
    ((uint4*)g_f116)[(size_t)row * 8 + lane] =
        pack8(make_float4(sa.x * fs, sa.y * fs, sa.z * fs, sa.w * fs),
              make_float4(sb.x * fs, sb.y * fs, sb.z * fs, sb.w * fs));
    uint4 xo = __ldg((const uint4*)g_x16 + (size_t)row * 8 + lane);
    float4 a0, a1;
    cvt8(a0, a1, xo);
    a0.x = a0.x * rsf + sa.x * inv; a0.y = a0.y * rsf + sa.y * inv;
    a0.z = a0.z * rsf + sa.z * inv; a0.w = a0.w * rsf + sa.w * inv;
    a1.x = a1.x * rsf + sb.x * inv; a1.y = a1.y * rsf + sb.y * inv;
    a1.z = a1.z * rsf + sb.z * inv; a1.w = a1.w * rsf + sb.w * inv;
    ((uint4*)g_acc16)[(size_t)row * 8 + lane] = pack8(a0, a1);
}

// Layer 2 (per graph): result = acc16 + normalize(gather(f116)); zeroes cnt for next call
__global__ void k_l2g(int rowbase, int nrows, float* __restrict__ out) {
    int t = blockIdx.x * blockDim.x + threadIdx.x;
    int lrow = t >> 3, lane = t & 7;
    if (lrow >= nrows) return;
    int row = rowbase + lrow;
    int beg = __ldg(g_rowptr + row);
    int deg = __ldg(g_cnt + row);
    float4 sa, sb;
    gather8((const uint4*)g_f116, beg, beg + deg, lane, sa, sb);
    if (lane == 0) g_cnt[row] = 0;    // last consumer of this row's counter
    float inv = norm_inv8(sa, sb);
    uint4 araw = ((const uint4*)g_acc16)[(size_t)row * 8 + lane];
    float4 a0, a1;
    cvt8(a0, a1, araw);
    a0.x += sa.x * inv; a0.y += sa.y * inv; a0.z += sa.z * inv; a0.w += sa.w * inv;
    a1.x += sb.x * inv; a1.y += sb.y * inv; a1.z += sb.z * inv; a1.w += sb.w * inv;
    if (row >= NU && row < R1) {
        ((uint4*)g_ili)[(size_t)(row - NU) * 8 + lane] = pack8(a0, a1);
        return;
    }
    float4* d;
    if (row < NU)            d = (float4*)out + (size_t)row * 16;
    else if (row < R1 + NU)  d = (float4*)out + ((size_t)NU + (row - R1)) * 16;
    else if (row < R2)       d = (float4*)out + ((size_t)3 * NU + NB + (row - R1 - NU)) * 16;
    else if (row < R2 + NU)  d = (float4*)out + ((size_t)2 * NU + (row - R2)) * 16;
    else                     d = (float4*)out + ((size_t)3 * NU + 2 * NB + (row - R2 - NU)) * 16;
    d[lane * 2]     = a0;
    d[lane * 2 + 1] = a1;
}

// Bundle aggregation: out[3U+b] = (1/max(deg,1)) * sum IL_i; zeroes agg counters
__global__ void k_agg(float* __restrict__ out) {
    int t = blockIdx.x * blockDim.x + threadIdx.x;
    int row = t >> 3, lane = t & 7;
    if (row >= NB) return;
    int grow = R3 + row;
    int beg = __ldg(g_rowptr + grow);
    int deg = __ldg(g_cnt + grow);
    float4 sa, sb;
    gather8((const uint4*)g_ili, beg, beg + deg, lane, sa, sb);
    if (lane == 0) g_cnt[grow] = 0;
    float fac = 1.f / fmaxf((float)deg, 1.f);
    sa.x *= fac; sa.y *= fac; sa.z *= fac; sa.w *= fac;
    sb.x *= fac; sb.y *= fac; sb.z *= fac; sb.w *= fac;
    float4* d = (float4*)out + ((size_t)3 * NU + row) * 16;
    d[lane * 2]     = sa;
    d[lane * 2 + 1] = sb;
}

// ---------------- host: 3-stream pipelined capture ----------------
struct PipeCtx {
    cudaStream_t sB, sC;
    cudaEvent_t evFork, evB, evC;
    PipeCtx() {
        cudaStreamCreateWithFlags(&sB, cudaStreamNonBlocking);
        cudaStreamCreateWithFlags(&sC, cudaStreamNonBlocking);
        cudaEventCreateWithFlags(&evFork, cudaEventDisableTiming);
        cudaEventCreateWithFlags(&evB, cudaEventDisableTiming);
        cudaEventCreateWithFlags(&evC, cudaEventDisableTiming);
    }
};
static PipeCtx& ctx() { static PipeCtx c; return c; }

extern "C" void kernel_launch(void* const* d_in, const int* in_sizes, int n_in,
                              void* d_out, int out_size) {
    const float* users   = (const float*)d_in[0];
    const float* bundles = (const float*)d_in[1];
    const float* items   = (const float*)d_in[2];
    const int*   ui_idx  = (const int*)d_in[3];
    const int*   ub_idx  = (const int*)d_in[5];
    const int*   ubx_idx = (const int*)d_in[7];
    const int*   agg_idx = (const int*)d_in[9];
    int n0 = in_sizes[4], n1 = in_sizes[6], n2 = in_sizes[8], n3 = in_sizes[10];
    float* out = (float*)d_out;

    PipeCtx& px = ctx();
    cudaEventRecord(px.evFork, 0);
    cudaStreamWaitEvent(px.sB, px.evFork, 0);
    cudaStreamWaitEvent(px.sC, px.evFork, 0);

    // ---- chain A (default stream): graph 0 (UI) + agg graph + k_agg ----
    k_histg<<<gdiv(n0, T), T>>>(ui_idx, n0, 0, 0);
    k_histg<<<gdiv(n3, T), T>>>(agg_idx, n3, R3, EB3);
    k_scang<<<22, 1024>>>(0, 90000, 0, 0);
    k_scang<<<5, 1024>>>(R3, 20000, EB3, 22);
    k_scatg<<<gdiv(n0, T), T>>>(ui_idx + n0, n0, 0, 0);
    k_scatg<<<gdiv(n3, T), T>>>(agg_idx + n3, n3, EB3, 0);
    k_prepg<<<gdiv(90000 * 16 + 64, T), T>>>((const float4*)users, (const float4*)items,
                                             0, 90000, 0, 27);
    k_l1g<<<gdiv(90000LL * 8, T), T>>>(0, 90000);
    k_l2g<<<gdiv(90000LL * 8, T), T>>>(0, 90000, out);
    k_agg<<<gdiv((long long)NB * 8, T), T>>>(out);

    // ---- chain B (stream sB): graph 1 (UB) ----
    k_histg<<<gdiv(n1, T), T, 0, px.sB>>>(ub_idx, n1, R1, EB1);
    k_scang<<<18, 1024, 0, px.sB>>>(R1, 70000, EB1, 27);
    k_scatg<<<gdiv(n1, T), T, 0, px.sB>>>(ub_idx + n1, n1, EB1, R1);
    k_prepg<<<gdiv(70000 * 16 + 64, T), T, 0, px.sB>>>((const float4*)users,
                                                       (const float4*)bundles,
                                                       R1, 70000, 27, 18);
    k_l1g<<<gdiv(70000LL * 8, T), T, 0, px.sB>>>(R1, 70000);
    k_l2g<<<gdiv(70000LL * 8, T), T, 0, px.sB>>>(R1, 70000, out);

    // ---- chain C (stream sC): graph 2 (UBX) ----
    k_histg<<<gdiv(n2, T), T, 0, px.sC>>>(ubx_idx, n2, R2, EB2);
    k_scang<<<18, 1024, 0, px.sC>>>(R2, 70000, EB2, 45);
    k_scatg<<<gdiv(n2, T), T, 0, px.sC>>>(ubx_idx + n2, n2, EB2, R2);
    k_prepg<<<gdiv(70000 * 16 + 64, T), T, 0, px.sC>>>((const float4*)users,
                                                       (const float4*)bundles,
                                                       R2, 70000, 45, 19);
    k_l1g<<<gdiv(70000LL * 8, T), T, 0, px.sC>>>(R2, 70000);
    k_l2g<<<gdiv(70000LL * 8, T), T, 0, px.sC>>>(R2, 70000, out);

    // ---- join ----
    cudaEventRecord(px.evB, px.sB);
    cudaEventRecord(px.evC, px.sC);
    cudaStreamWaitEvent(0, px.evB, 0);
    cudaStreamWaitEvent(0, px.evC, 0);
}

// round 14
// speedup vs baseline: 1.2389x; 1.0368x over previous
#include <cuda_runtime.h>
#include <cuda_fp16.h>

#define DD 64
#define NU 50000
#define NB 20000
#define NI 40000
#define R1 90000
#define R2 160000
#define R3 230000
#define NROWS 250000
#define NPROWS 230000
// per-graph edge-region bases (capacities exceed exact sizes 2.0M/1.2M/1.6M/0.3M)
#define EB1 2050000
#define EB2 3300000
#define EB3 4950000
#define EMAX 5300000
#define T 256

// ---- device scratch (no allocation; zero-initialized at load) ----
__device__ __half g_x16  [(size_t)NPROWS * DD];
__device__ __half g_f116 [(size_t)NPROWS * DD];
__device__ __half g_ili  [(size_t)NI * DD];
__device__ __half g_acc16[(size_t)NPROWS * DD];
__device__ int    g_ecol[EMAX];
__device__ int    g_lo  [EMAX];
__device__ int    g_cnt [NROWS];       // degree counters; zeroed by last consumer
__device__ int    g_rowptr[NROWS];     // row start (includes edge-region base)
__device__ unsigned long long g_bstate[64];

static inline unsigned gdiv(long long a, int b) { return (unsigned)((a + b - 1) / b); }

// ---------------- per-graph histogram ----------------
__global__ void k_histg(const int* __restrict__ rows, int nE, int rowbase, int lobase) {
    int e = blockIdx.x * blockDim.x + threadIdx.x;
    if (e >= nE) return;
    int grow = __ldg(rows + e) + rowbase;
    int slot = atomicAdd(&g_cnt[grow], 1);
    g_lo[lobase + e] = (grow << 8) | slot;
}

// ---------------- per-graph decoupled-lookback exclusive scan ----------------
__global__ void __launch_bounds__(1024) k_scang(int rowbase, int nrows, int ebase, int bso) {
    __shared__ int wsum[32];
    __shared__ int s_prefix;
    int tid = threadIdx.x, lane = tid & 31, wid = tid >> 5;
    int bid = blockIdx.x;
    int i0 = bid * 4096 + tid * 4;
    int v[4];
    #pragma unroll
    for (int j = 0; j < 4; j++) v[j] = (i0 + j < nrows) ? g_cnt[rowbase + i0 + j] : 0;
    int tsum = v[0] + v[1] + v[2] + v[3];
    int sc = tsum;
    #pragma unroll
    for (int o = 1; o < 32; o <<= 1) {
        int u = __shfl_up_sync(0xffffffffu, sc, o);
        if (lane >= o) sc += u;
    }
    if (lane == 31) wsum[wid] = sc;
    __syncthreads();
    if (wid == 0) {
        int ws = wsum[lane];
        int sw = ws;
        #pragma unroll
        for (int o = 1; o < 32; o <<= 1) {
            int u = __shfl_up_sync(0xffffffffu, sw, o);
            if (lane >= o) sw += u;
        }
        wsum[lane] = sw - ws;
        int agg = __shfl_sync(0xffffffffu, sw, 31);
        if (lane == 0)
            atomicExch(&g_bstate[bso + bid],
                       (bid == 0 ? (2ULL << 32) : (1ULL << 32)) | (unsigned)agg);
        int prefix = 0;
        if (bid > 0) {
            int j = bid - 1;
            for (;;) {
                int idx = j - lane;
                unsigned long long s = (idx >= 0) ? atomicAdd(&g_bstate[bso + idx], 0ULL)
                                                  : (2ULL << 32);
                unsigned flag = (unsigned)(s >> 32);
                unsigned invb = __ballot_sync(0xffffffffu, flag == 0u);
                unsigned preb = __ballot_sync(0xffffffffu, flag == 2u);
                int p  = preb ? (__ffs(preb) - 1) : 32;
                int iv = invb ? (__ffs(invb) - 1) : 32;
                if (iv < p) continue;
                int cnt = (p < 32) ? (p + 1) : 32;
                int val = (lane < cnt) ? (int)(s & 0xffffffffu) : 0;
                #pragma unroll
                for (int o = 16; o; o >>= 1) val += __shfl_xor_sync(0xffffffffu, val, o);
                prefix += val;
                if (p < 32) break;
                j -= 32;
            }
            if (lane == 0)
                atomicExch(&g_bstate[bso + bid],
                           (2ULL << 32) | (unsigned)(prefix + agg));
        }
        if (lane == 0) s_prefix = prefix;
    }
    __syncthreads();
    int excl = s_prefix + wsum[wid] + (sc - tsum);
    #pragma unroll
    for (int j = 0; j < 4; j++) {
        if (i0 + j < nrows) g_rowptr[rowbase + i0 + j] = ebase + excl;
        excl += v[j];
    }
}

// ---------------- per-graph atomic-free scatter ----------------
__global__ void k_scatg(const int* __restrict__ cols, int nE, int lobase, int co) {
    int e = blockIdx.x * blockDim.x + threadIdx.x;
    if (e >= nE) return;
    int packed = g_lo[lobase + e];
    int pos = __ldg(g_rowptr + (packed >> 8)) + (packed & 255);
    g_ecol[pos] = __ldg(cols + e) + co;
}

// ---------------- per-graph prep: col-scaled fp16 features + bstate re-zero ----------------
__global__ void k_prepg(const float4* __restrict__ srcA, const float4* __restrict__ srcB,
                        int rowbase, int nrows, int zbase, int zcnt) {
    int t = blockIdx.x * blockDim.x + threadIdx.x;
    int nq = nrows * 16;
    if (t < nq) {
        int lrow = t >> 4, sub = t & 15;
        int grow = rowbase + lrow;
        int deg = g_cnt[grow];
        float nf = (deg > 0) ? 1.f / (sqrtf((float)deg) + 1e-8f) : 1.f;
        const float4* xp = (lrow < NU) ? srcA + (size_t)lrow * 16
                                       : srcB + (size_t)(lrow - NU) * 16;
        float4 v = __ldg(xp + sub);
        __half2 h0 = __float22half2_rn(make_float2(v.x * nf, v.y * nf));
        __half2 h1 = __float22half2_rn(make_float2(v.z * nf, v.w * nf));
        ((uint2*)g_x16)[(size_t)grow * 16 + sub] = make_uint2(*(unsigned*)&h0, *(unsigned*)&h1);
    } else {
        int z = t - nq;
        if (z < zcnt) g_bstate[zbase + z] = 0ULL;
    }
}

// ---------------- gathers: 8 lanes/row, unroll 4 (round-9 proven core) ----------------
__device__ __forceinline__ void hadd8(float4& a, float4& b, uint4 raw) {
    __half2* h = (__half2*)&raw;
    float2 f0 = __half22float2(h[0]), f1 = __half22float2(h[1]);
    float2 f2 = __half22float2(h[2]), f3 = __half22float2(h[3]);
    a.x += f0.x; a.y += f0.y; a.z += f1.x; a.w += f1.y;
    b.x += f2.x; b.y += f2.y; b.z += f3.x; b.w += f3.y;
}

__device__ __forceinline__ void cvt8(float4& a, float4& b, uint4 raw) {
    __half2* h = (__half2*)&raw;
    float2 f0 = __half22float2(h[0]), f1 = __half22float2(h[1]);
    float2 f2 = __half22float2(h[2]), f3 = __half22float2(h[3]);
    a = make_float4(f0.x, f0.y, f1.x, f1.y);
    b = make_float4(f2.x, f2.y, f3.x, f3.y);
}

__device__ __forceinline__ uint4 pack8(float4 a, float4 b) {
    __half2 h0 = __float22half2_rn(make_float2(a.x, a.y));
    __half2 h1 = __float22half2_rn(make_float2(a.z, a.w));
    __half2 h2 = __float22half2_rn(make_float2(b.x, b.y));
    __half2 h3 = __float22half2_rn(make_float2(b.z, b.w));
    return make_uint4(*(unsigned*)&h0, *(unsigned*)&h1, *(unsigned*)&h2, *(unsigned*)&h3);
}

__device__ __forceinline__ void gather8(const uint4* __restrict__ src, int beg, int end,
                                        int lane, float4& sa, float4& sb) {
    sa = make_float4(0.f, 0.f, 0.f, 0.f);
    sb = make_float4(0.f, 0.f, 0.f, 0.f);
    int i = beg;
    for (; i + 4 <= end; i += 4) {
        int c0 = __ldg(g_ecol + i),     c1 = __ldg(g_ecol + i + 1);
        int c2 = __ldg(g_ecol + i + 2), c3 = __ldg(g_ecol + i + 3);
        uint4 x0 = __ldg(src + (size_t)c0 * 8 + lane);
        uint4 x1 = __ldg(src + (size_t)c1 * 8 + lane);
        uint4 x2 = __ldg(src + (size_t)c2 * 8 + lane);
        uint4 x3 = __ldg(src + (size_t)c3 * 8 + lane);
        hadd8(sa, sb, x0); hadd8(sa, sb, x1); hadd8(sa, sb, x2); hadd8(sa, sb, x3);
    }
    for (; i < end; i++) {
        uint4 x0 = __ldg(src + (size_t)__ldg(g_ecol + i) * 8 + lane);
        hadd8(sa, sb, x0);
    }
}

__device__ __forceinline__ float norm_inv8(float4 a, float4 b) {
    float ss = a.x * a.x + a.y * a.y + a.z * a.z + a.w * a.w
             + b.x * b.x + b.y * b.y + b.z * b.z + b.w * b.w;
    #pragma unroll
    for (int o = 4; o; o >>= 1) ss += __shfl_xor_sync(0xffffffffu, ss, o, 8);
    return 1.f / fmaxf(sqrtf(ss), 1e-12f);
}

// Layer 1 (per graph): raw = gather(x16); f116 = raw*16*nf^2; acc16 = x16*rsf + normalize(raw)
__global__ void k_l1g(int rowbase, int nrows) {
    int t = blockIdx.x * blockDim.x + threadIdx.x;
    int lrow = t >> 3, lane = t & 7;
    if (lrow >= nrows) return;
    int row = rowbase + lrow;
    int beg = __ldg(g_rowptr + row);
    int deg = __ldg(g_cnt + row);
    float4 sa, sb;
    gather8((const uint4*)g_x16, beg, beg + deg, lane, sa, sb);
    float nf = (deg > 0) ? 1.f / (sqrtf((float)deg) + 1e-8f) : 1.f;
    float rsf = (deg > 0) ? (sqrtf((float)deg) + 1e-8f) : 1.f;
    float fs = 16.f * nf * nf;
    float inv = norm_inv8(sa, sb);
    ((uint4*)g_f116)[(size_t)row * 8 + lane] =
        pack8(make_float4(sa.x * fs, sa.y * fs, sa.z * fs, sa.w * fs),
              make_float4(sb.x * fs, sb.y * fs, sb.z * fs, sb.w * fs));
    uint4 xo = __ldg((const uint4*)g_x16 + (size_t)row * 8 + lane);
    float4 a0, a1;
    cvt8(a0, a1, xo);
    a0.x = a0.x * rsf + sa.x * inv; a0.y = a0.y * rsf + sa.y * inv;
    a0.z = a0.z * rsf + sa.z * inv; a0.w = a0.w * rsf + sa.w * inv;
    a1.x = a1.x * rsf + sb.x * inv; a1.y = a1.y * rsf + sb.y * inv;
    a1.z = a1.z * rsf + sb.z * inv; a1.w = a1.w * rsf + sb.w * inv;
    ((uint4*)g_acc16)[(size_t)row * 8 + lane] = pack8(a0, a1);
}

// Layer 2 (per graph): result = acc16 + normalize(gather(f116)); zeroes cnt for next call
__global__ void k_l2g(int rowbase, int nrows, float* __restrict__ out) {
    int t = blockIdx.x * blockDim.x + threadIdx.x;
    int lrow = t >> 3, lane = t & 7;
    if (lrow >= nrows) return;
    int row = rowbase + lrow;
    int beg = __ldg(g_rowptr + row);
    int deg = __ldg(g_cnt + row);
    float4 sa, sb;
    gather8((const uint4*)g_f116, beg, beg + deg, lane, sa, sb);
    if (lane == 0) g_cnt[row] = 0;    // last consumer of this row's counter
    float inv = norm_inv8(sa, sb);
    uint4 araw = ((const uint4*)g_acc16)[(size_t)row * 8 + lane];
    float4 a0, a1;
    cvt8(a0, a1, araw);
    a0.x += sa.x * inv; a0.y += sa.y * inv; a0.z += sa.z * inv; a0.w += sa.w * inv;
    a1.x += sb.x * inv; a1.y += sb.y * inv; a1.z += sb.z * inv; a1.w += sb.w * inv;
    if (row >= NU && row < R1) {
        ((uint4*)g_ili)[(size_t)(row - NU) * 8 + lane] = pack8(a0, a1);
        return;
    }
    float4* d;
    if (row < NU)            d = (float4*)out + (size_t)row * 16;
    else if (row < R1 + NU)  d = (float4*)out + ((size_t)NU + (row - R1)) * 16;
    else if (row < R2)       d = (float4*)out + ((size_t)3 * NU + NB + (row - R1 - NU)) * 16;
    else if (row < R2 + NU)  d = (float4*)out + ((size_t)2 * NU + (row - R2)) * 16;
    else                     d = (float4*)out + ((size_t)3 * NU + 2 * NB + (row - R2 - NU)) * 16;
    d[lane * 2]     = a0;
    d[lane * 2 + 1] = a1;
}

// Bundle aggregation; zeroes agg counters + stream-D bstate slots for next replay
__global__ void k_agg(float* __restrict__ out) {
    int t = blockIdx.x * blockDim.x + threadIdx.x;
    if (t < 5) g_bstate[22 + t] = 0ULL;
    int row = t >> 3, lane = t & 7;
    if (row >= NB) return;
    int grow = R3 + row;
    int beg = __ldg(g_rowptr + grow);
    int deg = __ldg(g_cnt + grow);
    float4 sa, sb;
    gather8((const uint4*)g_ili, beg, beg + deg, lane, sa, sb);
    if (lane == 0) g_cnt[grow] = 0;
    float fac = 1.f / fmaxf((float)deg, 1.f);
    sa.x *= fac; sa.y *= fac; sa.z *= fac; sa.w *= fac;
    sb.x *= fac; sb.y *= fac; sb.z *= fac; sb.w *= fac;
    float4* d = (float4*)out + ((size_t)3 * NU + row) * 16;
    d[lane * 2]     = sa;
    d[lane * 2 + 1] = sb;
}

// ---------------- host: 4-stream pipelined capture ----------------
struct PipeCtx {
    cudaStream_t sB, sC, sD;
    cudaEvent_t evFork, evB, evC, evD;
    PipeCtx() {
        cudaStreamCreateWithFlags(&sB, cudaStreamNonBlocking);
        cudaStreamCreateWithFlags(&sC, cudaStreamNonBlocking);
        cudaStreamCreateWithFlags(&sD, cudaStreamNonBlocking);
        cudaEventCreateWithFlags(&evFork, cudaEventDisableTiming);
        cudaEventCreateWithFlags(&evB, cudaEventDisableTiming);
        cudaEventCreateWithFlags(&evC, cudaEventDisableTiming);
        cudaEventCreateWithFlags(&evD, cudaEventDisableTiming);
    }
};
static PipeCtx& ctx() { static PipeCtx c; return c; }

extern "C" void kernel_launch(void* const* d_in, const int* in_sizes, int n_in,
                              void* d_out, int out_size) {
    const float* users   = (const float*)d_in[0];
    const float* bundles = (const float*)d_in[1];
    const float* items   = (const float*)d_in[2];
    const int*   ui_idx  = (const int*)d_in[3];
    const int*   ub_idx  = (const int*)d_in[5];
    const int*   ubx_idx = (const int*)d_in[7];
    const int*   agg_idx = (const int*)d_in[9];
    int n0 = in_sizes[4], n1 = in_sizes[6], n2 = in_sizes[8], n3 = in_sizes[10];
    float* out = (float*)d_out;

    PipeCtx& px = ctx();
    cudaEventRecord(px.evFork, 0);
    cudaStreamWaitEvent(px.sB, px.evFork, 0);
    cudaStreamWaitEvent(px.sC, px.evFork, 0);
    cudaStreamWaitEvent(px.sD, px.evFork, 0);

    // ---- chain A (default stream): graph 0 (UI) propagation ----
    k_histg<<<gdiv(n0, T), T>>>(ui_idx, n0, 0, 0);
    k_scang<<<22, 1024>>>(0, 90000, 0, 0);
    k_scatg<<<gdiv(n0, T), T>>>(ui_idx + n0, n0, 0, 0);
    k_prepg<<<gdiv(90000 * 16 + 32, T), T>>>((const float4*)users, (const float4*)items,
                                             0, 90000, 0, 22);
    k_l1g<<<gdiv(90000LL * 8, T), T>>>(0, 90000);
    k_l2g<<<gdiv(90000LL * 8, T), T>>>(0, 90000, out);

    // ---- chain D (stream sD): agg-graph CSR build (consumed only by k_agg) ----
    k_histg<<<gdiv(n3, T), T, 0, px.sD>>>(agg_idx, n3, R3, EB3);
    k_scang<<<5, 1024, 0, px.sD>>>(R3, 20000, EB3, 22);
    k_scatg<<<gdiv(n3, T), T, 0, px.sD>>>(agg_idx + n3, n3, EB3, 0);
    cudaEventRecord(px.evD, px.sD);

    // ---- chain B (stream sB): graph 1 (UB) ----
    k_histg<<<gdiv(n1, T), T, 0, px.sB>>>(ub_idx, n1, R1, EB1);
    k_scang<<<18, 1024, 0, px.sB>>>(R1, 70000, EB1, 27);
    k_scatg<<<gdiv(n1, T), T, 0, px.sB>>>(ub_idx + n1, n1, EB1, R1);
    k_prepg<<<gdiv(70000 * 16 + 32, T), T, 0, px.sB>>>((const float4*)users,
                                                       (const float4*)bundles,
                                                       R1, 70000, 27, 18);
    k_l1g<<<gdiv(70000LL * 8, T), T, 0, px.sB>>>(R1, 70000);
    k_l2g<<<gdiv(70000LL * 8, T), T, 0, px.sB>>>(R1, 70000, out);

    // ---- chain C (stream sC): graph 2 (UBX) ----
    k_histg<<<gdiv(n2, T), T, 0, px.sC>>>(ubx_idx, n2, R2, EB2);
    k_scang<<<18, 1024, 0, px.sC>>>(R2, 70000, EB2, 45);
    k_scatg<<<gdiv(n2, T), T, 0, px.sC>>>(ubx_idx + n2, n2, EB2, R2);
    k_prepg<<<gdiv(70000 * 16 + 32, T), T, 0, px.sC>>>((const float4*)users,
                                                       (const float4*)bundles,
                                                       R2, 70000, 45, 19);
    k_l1g<<<gdiv(70000LL * 8, T), T, 0, px.sC>>>(R2, 70000);
    k_l2g<<<gdiv(70000LL * 8, T), T, 0, px.sC>>>(R2, 70000, out);

    // ---- join: k_agg needs chain A's IL_i + chain D's agg CSR ----
    cudaStreamWaitEvent(0, px.evD, 0);
    k_agg<<<gdiv((long long)NB * 8, T), T>>>(out);
    cudaEventRecord(px.evB, px.sB);
    cudaEventRecord(px.evC, px.sC);
    cudaStreamWaitEvent(0, px.evB, 0);
    cudaStreamWaitEvent(0, px.evC, 0);
}

// round 16
// speedup vs baseline: 1.2521x; 1.0106x over previous
#include <cuda_runtime.h>
#include <cuda_fp16.h>

#define DD 64
#define NU 50000
#define NB 20000
#define NI 40000
#define R1 90000
#define R2 160000
#define R3 230000
#define NROWS 250000
#define NPROWS 230000
// per-graph edge-region bases (capacities exceed exact sizes 2.0M/1.2M/1.6M/0.3M)
#define EB1 2050000
#define EB2 3300000
#define EB3 4950000
#define EMAX 5300000
#define T 256

// ---- device scratch (no allocation; zero-initialized at load) ----
__device__ __half g_x16  [(size_t)NPROWS * DD];
__device__ __half g_f116 [(size_t)NPROWS * DD];
__device__ __half g_ili  [(size_t)NI * DD];
__device__ __half g_acc16[(size_t)NPROWS * DD];
__device__ int    g_ecol[EMAX];
__device__ int    g_lo  [EMAX];
__device__ int    g_cnt [NROWS];       // degree counters; zeroed by last consumer
__device__ int    g_rowptr[NROWS];     // row start (includes edge-region base)
__device__ unsigned long long g_bstate[64];

static inline unsigned gdiv(long long a, int b) { return (unsigned)((a + b - 1) / b); }

// ---------------- per-graph histogram ----------------
__global__ void k_histg(const int* __restrict__ rows, int nE, int rowbase, int lobase) {
    int e = blockIdx.x * blockDim.x + threadIdx.x;
    if (e >= nE) return;
    int grow = __ldg(rows + e) + rowbase;
    int slot = atomicAdd(&g_cnt[grow], 1);
    g_lo[lobase + e] = (grow << 8) | slot;
}

// ---------------- per-graph decoupled-lookback exclusive scan ----------------
__global__ void __launch_bounds__(1024) k_scang(int rowbase, int nrows, int ebase, int bso) {
    __shared__ int wsum[32];
    __shared__ int s_prefix;
    int tid = threadIdx.x, lane = tid & 31, wid = tid >> 5;
    int bid = blockIdx.x;
    int i0 = bid * 4096 + tid * 4;
    int v[4];
    #pragma unroll
    for (int j = 0; j < 4; j++) v[j] = (i0 + j < nrows) ? g_cnt[rowbase + i0 + j] : 0;
    int tsum = v[0] + v[1] + v[2] + v[3];
    int sc = tsum;
    #pragma unroll
    for (int o = 1; o < 32; o <<= 1) {
        int u = __shfl_up_sync(0xffffffffu, sc, o);
        if (lane >= o) sc += u;
    }
    if (lane == 31) wsum[wid] = sc;
    __syncthreads();
    if (wid == 0) {
        int ws = wsum[lane];
        int sw = ws;
        #pragma unroll
        for (int o = 1; o < 32; o <<= 1) {
            int u = __shfl_up_sync(0xffffffffu, sw, o);
            if (lane >= o) sw += u;
        }
        wsum[lane] = sw - ws;
        int agg = __shfl_sync(0xffffffffu, sw, 31);
        if (lane == 0)
            atomicExch(&g_bstate[bso + bid],
                       (bid == 0 ? (2ULL << 32) : (1ULL << 32)) | (unsigned)agg);
        int prefix = 0;
        if (bid > 0) {
            int j = bid - 1;
            for (;;) {
                int idx = j - lane;
                unsigned long long s = (idx >= 0) ? atomicAdd(&g_bstate[bso + idx], 0ULL)
                                                  : (2ULL << 32);
                unsigned flag = (unsigned)(s >> 32);
                unsigned invb = __ballot_sync(0xffffffffu, flag == 0u);
                unsigned preb = __ballot_sync(0xffffffffu, flag == 2u);
                int p  = preb ? (__ffs(preb) - 1) : 32;
                int iv = invb ? (__ffs(invb) - 1) : 32;
                if (iv < p) continue;
                int cnt = (p < 32) ? (p + 1) : 32;
                int val = (lane < cnt) ? (int)(s & 0xffffffffu) : 0;
                #pragma unroll
                for (int o = 16; o; o >>= 1) val += __shfl_xor_sync(0xffffffffu, val, o);
                prefix += val;
                if (p < 32) break;
                j -= 32;
            }
            if (lane == 0)
                atomicExch(&g_bstate[bso + bid],
                           (2ULL << 32) | (unsigned)(prefix + agg));
        }
        if (lane == 0) s_prefix = prefix;
    }
    __syncthreads();
    int excl = s_prefix + wsum[wid] + (sc - tsum);
    #pragma unroll
    for (int j = 0; j < 4; j++) {
        if (i0 + j < nrows) g_rowptr[rowbase + i0 + j] = ebase + excl;
        excl += v[j];
    }
}

// ---------------- per-graph atomic-free scatter ----------------
__global__ void k_scatg(const int* __restrict__ cols, int nE, int lobase, int co) {
    int e = blockIdx.x * blockDim.x + threadIdx.x;
    if (e >= nE) return;
    int packed = g_lo[lobase + e];
    int pos = __ldg(g_rowptr + (packed >> 8)) + (packed & 255);
    g_ecol[pos] = __ldg(cols + e) + co;
}

// ---------------- per-graph prep: col-scaled fp16 features (needs hist only) ----------------
__global__ void k_prepg(const float4* __restrict__ srcA, const float4* __restrict__ srcB,
                        int rowbase, int nrows) {
    int t = blockIdx.x * blockDim.x + threadIdx.x;
    if (t >= nrows * 16) return;
    int lrow = t >> 4, sub = t & 15;
    int grow = rowbase + lrow;
    int deg = g_cnt[grow];
    float nf = (deg > 0) ? 1.f / (sqrtf((float)deg) + 1e-8f) : 1.f;
    const float4* xp = (lrow < NU) ? srcA + (size_t)lrow * 16
                                   : srcB + (size_t)(lrow - NU) * 16;
    float4 v = __ldg(xp + sub);
    __half2 h0 = __float22half2_rn(make_float2(v.x * nf, v.y * nf));
    __half2 h1 = __float22half2_rn(make_float2(v.z * nf, v.w * nf));
    ((uint2*)g_x16)[(size_t)grow * 16 + sub] = make_uint2(*(unsigned*)&h0, *(unsigned*)&h1);
}

// ---------------- gathers: 8 lanes/row, unroll 4 (round-9 proven core) ----------------
__device__ __forceinline__ void hadd8(float4& a, float4& b, uint4 raw) {
    __half2* h = (__half2*)&raw;
    float2 f0 = __half22float2(h[0]), f1 = __half22float2(h[1]);
    float2 f2 = __half22float2(h[2]), f3 = __half22float2(h[3]);
    a.x += f0.x; a.y += f0.y; a.z += f1.x; a.w += f1.y;
    b.x += f2.x; b.y += f2.y; b.z += f3.x; b.w += f3.y;
}

__device__ __forceinline__ void cvt8(float4& a, float4& b, uint4 raw) {
    __half2* h = (__half2*)&raw;
    float2 f0 = __half22float2(h[0]), f1 = __half22float2(h[1]);
    float2 f2 = __half22float2(h[2]), f3 = __half22float2(h[3]);
    a = make_float4(f0.x, f0.y, f1.x, f1.y);
    b = make_float4(f2.x, f2.y, f3.x, f3.y);
}

__device__ __forceinline__ uint4 pack8(float4 a, float4 b) {
    __half2 h0 = __float22half2_rn(make_float2(a.x, a.y));
    __half2 h1 = __float22half2_rn(make_float2(a.z, a.w));
    __half2 h2 = __float22half2_rn(make_float2(b.x, b.y));
    __half2 h3 = __float22half2_rn(make_float2(b.z, b.w));
    return make_uint4(*(unsigned*)&h0, *(unsigned*)&h1, *(unsigned*)&h2, *(unsigned*)&h3);
}

__device__ __forceinline__ void gather8(const uint4* __restrict__ src, int beg, int end,
                                        int lane, float4& sa, float4& sb) {
    sa = make_float4(0.f, 0.f, 0.f, 0.f);
    sb = make_float4(0.f, 0.f, 0.f, 0.f);
    int i = beg;
    for (; i + 4 <= end; i += 4) {
        int c0 = __ldg(g_ecol + i),     c1 = __ldg(g_ecol + i + 1);
        int c2 = __ldg(g_ecol + i + 2), c3 = __ldg(g_ecol + i + 3);
        uint4 x0 = __ldg(src + (size_t)c0 * 8 + lane);
        uint4 x1 = __ldg(src + (size_t)c1 * 8 + lane);
        uint4 x2 = __ldg(src + (size_t)c2 * 8 + lane);
        uint4 x3 = __ldg(src + (size_t)c3 * 8 + lane);
        hadd8(sa, sb, x0); hadd8(sa, sb, x1); hadd8(sa, sb, x2); hadd8(sa, sb, x3);
    }
    for (; i < end; i++) {
        uint4 x0 = __ldg(src + (size_t)__ldg(g_ecol + i) * 8 + lane);
        hadd8(sa, sb, x0);
    }
}

__device__ __forceinline__ float norm_inv8(float4 a, float4 b) {
    float ss = a.x * a.x + a.y * a.y + a.z * a.z + a.w * a.w
             + b.x * b.x + b.y * b.y + b.z * b.z + b.w * b.w;
    #pragma unroll
    for (int o = 4; o; o >>= 1) ss += __shfl_xor_sync(0xffffffffu, ss, o, 8);
    return 1.f / fmaxf(sqrtf(ss), 1e-12f);
}

// Layer 1 (per graph) + bstate re-zero (safe: runs after scan/scat/prep join)
__global__ void k_l1g(int rowbase, int nrows, int zbase, int zcnt) {
    int t = blockIdx.x * blockDim.x + threadIdx.x;
    if (t < zcnt) g_bstate[zbase + t] = 0ULL;
    int lrow = t >> 3, lane = t & 7;
    if (lrow >= nrows) return;
    int row = rowbase + lrow;
    int beg = __ldg(g_rowptr + row);
    int deg = __ldg(g_cnt + row);
    float4 sa, sb;
    gather8((const uint4*)g_x16, beg, beg + deg, lane, sa, sb);
    float nf = (deg > 0) ? 1.f / (sqrtf((float)deg) + 1e-8f) : 1.f;
    float rsf = (deg > 0) ? (sqrtf((float)deg) + 1e-8f) : 1.f;
    float fs = 16.f * nf * nf;
    float inv = norm_inv8(sa, sb);
    ((uint4*)g_f116)[(size_t)row * 8 + lane] =
        pack8(make_float4(sa.x * fs, sa.y * fs, sa.z * fs, sa.w * fs),
              make_float4(sb.x * fs, sb.y * fs, sb.z * fs, sb.w * fs));
    uint4 xo = __ldg((const uint4*)g_x16 + (size_t)row * 8 + lane);
    float4 a0, a1;
    cvt8(a0, a1, xo);
    a0.x = a0.x * rsf + sa.x * inv; a0.y = a0.y * rsf + sa.y * inv;
    a0.z = a0.z * rsf + sa.z * inv; a0.w = a0.w * rsf + sa.w * inv;
    a1.x = a1.x * rsf + sb.x * inv; a1.y = a1.y * rsf + sb.y * inv;
    a1.z = a1.z * rsf + sb.z * inv; a1.w = a1.w * rsf + sb.w * inv;
    ((uint4*)g_acc16)[(size_t)row * 8 + lane] = pack8(a0, a1);
}

// Layer 2 (per graph): result = acc16 + normalize(gather(f116)); zeroes cnt for next call
__global__ void k_l2g(int rowbase, int nrows, float* __restrict__ out) {
    int t = blockIdx.x * blockDim.x + threadIdx.x;
    int lrow = t >> 3, lane = t & 7;
    if (lrow >= nrows) return;
    int row = rowbase + lrow;
    int beg = __ldg(g_rowptr + row);
    int deg = __ldg(g_cnt + row);
    float4 sa, sb;
    gather8((const uint4*)g_f116, beg, beg + deg, lane, sa, sb);
    if (lane == 0) g_cnt[row] = 0;    // last consumer of this row's counter
    float inv = norm_inv8(sa, sb);
    uint4 araw = ((const uint4*)g_acc16)[(size_t)row * 8 + lane];
    float4 a0, a1;
    cvt8(a0, a1, araw);
    a0.x += sa.x * inv; a0.y += sa.y * inv; a0.z += sa.z * inv; a0.w += sa.w * inv;
    a1.x += sb.x * inv; a1.y += sb.y * inv; a1.z += sb.z * inv; a1.w += sb.w * inv;
    if (row >= NU && row < R1) {
        ((uint4*)g_ili)[(size_t)(row - NU) * 8 + lane] = pack8(a0, a1);
        return;
    }
    float4* d;
    if (row < NU)            d = (float4*)out + (size_t)row * 16;
    else if (row < R1 + NU)  d = (float4*)out + ((size_t)NU + (row - R1)) * 16;
    else if (row < R2)       d = (float4*)out + ((size_t)3 * NU + NB + (row - R1 - NU)) * 16;
    else if (row < R2 + NU)  d = (float4*)out + ((size_t)2 * NU + (row - R2)) * 16;
    else                     d = (float4*)out + ((size_t)3 * NU + 2 * NB + (row - R2 - NU)) * 16;
    d[lane * 2]     = a0;
    d[lane * 2 + 1] = a1;
}

// Bundle aggregation; zeroes agg counters + stream-D bstate slots for next replay
__global__ void k_agg(float* __restrict__ out) {
    int t = blockIdx.x * blockDim.x + threadIdx.x;
    if (t < 5) g_bstate[22 + t] = 0ULL;
    int row = t >> 3, lane = t & 7;
    if (row >= NB) return;
    int grow = R3 + row;
    int beg = __ldg(g_rowptr + grow);
    int deg = __ldg(g_cnt + grow);
    float4 sa, sb;
    gather8((const uint4*)g_ili, beg, beg + deg, lane, sa, sb);
    if (lane == 0) g_cnt[grow] = 0;
    float fac = 1.f / fmaxf((float)deg, 1.f);
    sa.x *= fac; sa.y *= fac; sa.z *= fac; sa.w *= fac;
    sb.x *= fac; sb.y *= fac; sb.z *= fac; sb.w *= fac;
    float4* d = (float4*)out + ((size_t)3 * NU + row) * 16;
    d[lane * 2]     = sa;
    d[lane * 2 + 1] = sb;
}

// ---------------- host: 4-stream pipeline; sD doubles as prep worker ----------------
struct PipeCtx {
    cudaStream_t sB, sC, sD;
    cudaEvent_t evFork, evB, evC, evD;
    cudaEvent_t evHA, evHB, evHC;   // hist done (prep may start)
    cudaEvent_t evPA, evPB, evPC;   // prep done (l1 may start)
    PipeCtx() {
        cudaStreamCreateWithFlags(&sB, cudaStreamNonBlocking);
        cudaStreamCreateWithFlags(&sC, cudaStreamNonBlocking);
        cudaStreamCreateWithFlags(&sD, cudaStreamNonBlocking);
        cudaEventCreateWithFlags(&evFork, cudaEventDisableTiming);
        cudaEventCreateWithFlags(&evB, cudaEventDisableTiming);
        cudaEventCreateWithFlags(&evC, cudaEventDisableTiming);
        cudaEventCreateWithFlags(&evD, cudaEventDisableTiming);
        cudaEventCreateWithFlags(&evHA, cudaEventDisableTiming);
        cudaEventCreateWithFlags(&evHB, cudaEventDisableTiming);
        cudaEventCreateWithFlags(&evHC, cudaEventDisableTiming);
        cudaEventCreateWithFlags(&evPA, cudaEventDisableTiming);
        cudaEventCreateWithFlags(&evPB, cudaEventDisableTiming);
        cudaEventCreateWithFlags(&evPC, cudaEventDisableTiming);
    }
};
static PipeCtx& ctx() { static PipeCtx c; return c; }

extern "C" void kernel_launch(void* const* d_in, const int* in_sizes, int n_in,
                              void* d_out, int out_size) {
    const float* users   = (const float*)d_in[0];
    const float* bundles = (const float*)d_in[1];
    const float* items   = (const float*)d_in[2];
    const int*   ui_idx  = (const int*)d_in[3];
    const int*   ub_idx  = (const int*)d_in[5];
    const int*   ubx_idx = (const int*)d_in[7];
    const int*   agg_idx = (const int*)d_in[9];
    int n0 = in_sizes[4], n1 = in_sizes[6], n2 = in_sizes[8], n3 = in_sizes[10];
    float* out = (float*)d_out;

    PipeCtx& px = ctx();
    cudaEventRecord(px.evFork, 0);
    cudaStreamWaitEvent(px.sB, px.evFork, 0);
    cudaStreamWaitEvent(px.sC, px.evFork, 0);
    cudaStreamWaitEvent(px.sD, px.evFork, 0);

    // ---- hists first (their events gate sD's preps) ----
    k_histg<<<gdiv(n0, T), T>>>(ui_idx, n0, 0, 0);
    cudaEventRecord(px.evHA, 0);
    k_histg<<<gdiv(n1, T), T, 0, px.sB>>>(ub_idx, n1, R1, EB1);
    cudaEventRecord(px.evHB, px.sB);
    k_histg<<<gdiv(n2, T), T, 0, px.sC>>>(ubx_idx, n2, R2, EB2);
    cudaEventRecord(px.evHC, px.sC);

    // ---- stream D: preps (A first — critical chain), then agg-graph build ----
    cudaStreamWaitEvent(px.sD, px.evHA, 0);
    k_prepg<<<gdiv(90000 * 16, T), T, 0, px.sD>>>((const float4*)users,
                                                  (const float4*)items, 0, 90000);
    cudaEventRecord(px.evPA, px.sD);
    cudaStreamWaitEvent(px.sD, px.evHB, 0);
    k_prepg<<<gdiv(70000 * 16, T), T, 0, px.sD>>>((const float4*)users,
                                                  (const float4*)bundles, R1, 70000);
    cudaEventRecord(px.evPB, px.sD);
    cudaStreamWaitEvent(px.sD, px.evHC, 0);
    k_prepg<<<gdiv(70000 * 16, T), T, 0, px.sD>>>((const float4*)users,
                                                  (const float4*)bundles, R2, 70000);
    cudaEventRecord(px.evPC, px.sD);
    k_histg<<<gdiv(n3, T), T, 0, px.sD>>>(agg_idx, n3, R3, EB3);
    k_scang<<<5, 1024, 0, px.sD>>>(R3, 20000, EB3, 22);
    k_scatg<<<gdiv(n3, T), T, 0, px.sD>>>(agg_idx + n3, n3, EB3, 0);
    cudaEventRecord(px.evD, px.sD);

    // ---- chain A (default): scan/scat overlap prepA; l1 waits both ----
    k_scang<<<22, 1024>>>(0, 90000, 0, 0);
    k_scatg<<<gdiv(n0, T), T>>>(ui_idx + n0, n0, 0, 0);
    cudaStreamWaitEvent(0, px.evPA, 0);
    k_l1g<<<gdiv(90000LL * 8, T), T>>>(0, 90000, 0, 22);
    k_l2g<<<gdiv(90000LL * 8, T), T>>>(0, 90000, out);

    // ---- chain B (sB) ----
    k_scang<<<18, 1024, 0, px.sB>>>(R1, 70000, EB1, 27);
    k_scatg<<<gdiv(n1, T), T, 0, px.sB>>>(ub_idx + n1, n1, EB1, R1);
    cudaStreamWaitEvent(px.sB, px.evPB, 0);
    k_l1g<<<gdiv(70000LL * 8, T), T, 0, px.sB>>>(R1, 70000, 27, 18);
    k_l2g<<<gdiv(70000LL * 8, T), T, 0, px.sB>>>(R1, 70000, out);

    // ---- chain C (sC) ----
    k_scang<<<18, 1024, 0, px.sC>>>(R2, 70000, EB2, 45);
    k_scatg<<<gdiv(n2, T), T, 0, px.sC>>>(ubx_idx + n2, n2, EB2, R2);
    cudaStreamWaitEvent(px.sC, px.evPC, 0);
    k_l1g<<<gdiv(70000LL * 8, T), T, 0, px.sC>>>(R2, 70000, 45, 19);
    k_l2g<<<gdiv(70000LL * 8, T), T, 0, px.sC>>>(R2, 70000, out);

    // ---- join: k_agg needs chain A's IL_i + chain D's agg CSR ----
    cudaStreamWaitEvent(0, px.evD, 0);
    k_agg<<<gdiv((long long)NB * 8, T), T>>>(out);
    cudaEventRecord(px.evB, px.sB);
    cudaEventRecord(px.evC, px.sC);
    cudaStreamWaitEvent(0, px.evB, 0);
    cudaStreamWaitEvent(0, px.evC, 0);
}